// round 2
// baseline (speedup 1.0000x reference)
#include <cuda_runtime.h>
#include <cstdint>
#include <math.h>

#define N_LEVELS 16
#define LOG2_T 19
#define TABLE_SIZE (1u << LOG2_T)
#define TABLE_MASK (TABLE_SIZE - 1u)

struct ResParams { float resm1[N_LEVELS]; };

__global__ void __launch_bounds__(256) hashgrid_kernel(
    const float* __restrict__ x,
    const float2* __restrict__ tables,
    float4* __restrict__ out,
    int n, ResParams rp)
{
    int i = blockIdx.x * blockDim.x + threadIdx.x;
    if (i >= n) return;

    // x is [N,3] row-major
    const float px = __ldg(&x[3 * i + 0]);
    const float py = __ldg(&x[3 * i + 1]);
    const float pz = __ldg(&x[3 * i + 2]);

    // Match reference: x_norm = (x + 1) / 2 in f32 (no FMA contraction)
    const float xn = __fmul_rn(__fadd_rn(px, 1.0f), 0.5f);
    const float yn = __fmul_rn(__fadd_rn(py, 1.0f), 0.5f);
    const float zn = __fmul_rn(__fadd_rn(pz, 1.0f), 0.5f);

    float2 f[N_LEVELS];

#pragma unroll
    for (int l = 0; l < N_LEVELS; l++) {
        const float r = rp.resm1[l];
        // scaled = x_norm * (res - 1); truncating cast == floor for s >= 0
        const uint32_t gx = (uint32_t)__fmul_rn(xn, r);
        const uint32_t gy = (uint32_t)__fmul_rn(yn, r);
        const uint32_t gz = (uint32_t)__fmul_rn(zn, r);
        const uint32_t h =
            (gx ^ (gy * 2654435761u) ^ (gz * 805459861u)) & TABLE_MASK;
        f[l] = __ldg(&tables[(size_t)l * TABLE_SIZE + h]);
    }

    // Each thread writes its own 128B output line: out[i][0..31]
    float4* o = out + (size_t)i * 8;
#pragma unroll
    for (int k = 0; k < 8; k++) {
        o[k] = make_float4(f[2 * k].x, f[2 * k].y,
                           f[2 * k + 1].x, f[2 * k + 1].y);
    }
}

extern "C" void kernel_launch(void* const* d_in, const int* in_sizes, int n_in,
                              void* d_out, int out_size)
{
    const float*  x      = (const float*)d_in[0];
    const float2* tables = (const float2*)d_in[1];
    float4*       out    = (float4*)d_out;

    const int n = in_sizes[0] / 3;  // x has N*3 elements

    // Resolutions computed with the same double-precision libm chain as the
    // Python reference: b = exp((log(2048) - log(16)) / 15); res_l = int(16 * b**l).
    // Levels 7/14/15 sit near integer boundaries, so this must be the *same*
    // rounding path (glibc log/exp/pow) as CPython's math module / float.__pow__.
    ResParams rp;
    {
        const double b = exp((log(2048.0) - log(16.0)) / 15.0);
        for (int l = 0; l < N_LEVELS; l++) {
            int res = (int)(16.0 * pow(b, (double)l));
            rp.resm1[l] = (float)res - 1.0f;
        }
    }

    const int threads = 256;
    const int blocks = (n + threads - 1) / threads;
    hashgrid_kernel<<<blocks, threads>>>(x, tables, out, n, rp);
}